// round 7
// baseline (speedup 1.0000x reference)
#include <cuda_runtime.h>
#include <math.h>

#define NQ 8
#define DIM 256
#define BATCH 8192
#define INPUT_DIM 3072
#define KVEC (INPUT_DIM / 4)
#define NCLS 10
#define NMERGED 17

#define N_CHAIN 128
#define N_GEMM 1024
#define NGRID (N_CHAIN + N_GEMM)   // 1152
#define NTHR 128

// ---------------------------------------------------------------------------
// Device scratch + sync state
// ---------------------------------------------------------------------------
__device__ float2 g_U[DIM * DIM];       // g_U[col*256 + k] = U[k][col]
__device__ float  g_A[DIM * DIM];       // Re(U^H Z0 U)
__device__ float  g_T1[81 * 256];
__device__ float  g_C[243 * 28];        // padded rows
__device__ int    g_barA, g_barB, g_barC;
__device__ volatile int g_done;
__device__ int    g_fin;

// ---------------------------------------------------------------------------
__device__ __forceinline__ float2 cmul(float2 a, float2 b) {
    return make_float2(a.x*b.x - a.y*b.y, a.x*b.y + a.y*b.x);
}
__device__ __forceinline__ float2 cfma(float2 a, float2 b, float2 c) {
    return make_float2(fmaf(a.x,b.x,fmaf(-a.y,b.y,c.x)),
                       fmaf(a.x,b.y,fmaf( a.y,b.x,c.y)));
}
__device__ __forceinline__ void u3fill(float t, float p, float d, float2 u[4]) {
    float ct = cosf(0.5f*t), st = sinf(0.5f*t);
    u[0] = make_float2(ct, 0.f);
    u[1] = make_float2(-cosf(d)*st, -sinf(d)*st);
    u[2] = make_float2( cosf(p)*st,  sinf(p)*st);
    u[3] = make_float2( cosf(p+d)*ct, sinf(p+d)*ct);
}
__device__ __forceinline__ unsigned long long ffma2(unsigned long long a,
                                                    unsigned long long b,
                                                    unsigned long long c) {
    unsigned long long d;
    asm("fma.rn.f32x2 %0, %1, %2, %3;" : "=l"(d) : "l"(a), "l"(b), "l"(c));
    return d;
}
__device__ __forceinline__ float pick3(int d, float sn, float cs) {
    return (d == 0) ? 1.f : ((d == 1) ? sn : cs);
}
// software barrier among the N_CHAIN chain blocks (all wave-1 resident)
__device__ __forceinline__ void chain_bar(int* ctr) {
    __threadfence();
    __syncthreads();
    if (threadIdx.x == 0) {
        atomicAdd(ctr, 1);
        while (*(volatile int*)ctr < N_CHAIN) { }
    }
    __syncthreads();
}

// ---------------------------------------------------------------------------
__global__ void __launch_bounds__(NTHR, 5)
mega(const float* __restrict__ x,    const float* __restrict__ fcw,
     const float* __restrict__ fcb,  const float* __restrict__ conv,
     const float* __restrict__ pool, const float* __restrict__ last,
     const float* __restrict__ outw, const float* __restrict__ outb,
     float* __restrict__ logits)
{
    __shared__ float2 elemBuf[71][16];
    __shared__ float2 mgbuf[2][16][16];
    __shared__ float2 lastbuf[2][16];
    __shared__ float2 mged[NMERGED][16];
    __shared__ float2 amp[2][256];
    __shared__ float2 sa[32][33];
    __shared__ float2 sb[16][33];

    const int t = threadIdx.x;
    const int bid = blockIdx.x;
    const int warp = t >> 5, lane = t & 31;

    if (bid < N_CHAIN) {
        // =================== CHAIN PATH (verified in R6) ===================
        const int convL[10] = {0,0,0,0,0,0,0,1,1,1};
        const int convI[10] = {0,2,4,6,1,3,5,0,2,1};
        const int poolL[6]  = {0,0,0,0,1,1};
        const int poolR[6]  = {0,1,2,3,0,1};
        const int l = t & 15;

        #pragma unroll
        for (int pass = 0; pass < 2; pass++) {
            int g = (t >> 4) + pass * 8;            // 0..15
            if (g < 10 && l < 5) {
                int L = convL[g], I = convI[g];
                const float* cw = conv + L * 120;
                float2 m[16];
                #pragma unroll
                for (int i = 0; i < 16; i++) m[i] = make_float2(0.f, 0.f);
                if (l == 0 || l == 4) {
                    float2 ua[4], ub[4];
                    if (l == 0) {
                        u3fill(cw[I*15+0],  cw[I*15+1],  cw[I*15+2],  ua);
                        u3fill(cw[(I+1)*15+3], cw[(I+1)*15+4], cw[(I+1)*15+5], ub);
                    } else {
                        u3fill(cw[I*15+9],  cw[I*15+10], cw[I*15+11], ua);
                        u3fill(cw[(I+1)*15+12], cw[(I+1)*15+13], cw[(I+1)*15+14], ub);
                    }
                    for (int ga = 0; ga < 2; ga++)
                        for (int gb = 0; gb < 2; gb++)
                            for (int ha = 0; ha < 2; ha++)
                                for (int hb = 0; hb < 2; hb++)
                                    m[(ga*2+gb)*4 + (ha*2+hb)] =
                                        cmul(ua[ga*2+ha], ub[gb*2+hb]);
                } else {
                    float phi = cw[I*15 + 5 + l];
                    float c = cosf(0.5f*phi), s = sinf(0.5f*phi);
                    if (l == 1) {                       // ZZ
                        m[0]  = make_float2(c,-s); m[5]  = make_float2(c, s);
                        m[10] = make_float2(c, s); m[15] = make_float2(c,-s);
                    } else if (l == 2) {                // YY
                        m[0]=m[5]=m[10]=m[15]=make_float2(c,0.f);
                        m[3]  = make_float2(0.f, s); m[6]  = make_float2(0.f,-s);
                        m[9]  = make_float2(0.f,-s); m[12] = make_float2(0.f, s);
                    } else {                            // XX
                        m[0]=m[5]=m[10]=m[15]=make_float2(c,0.f);
                        m[3]=m[6]=m[9]=m[12]=make_float2(0.f,-s);
                    }
                }
                #pragma unroll
                for (int i = 0; i < 16; i++) elemBuf[g*5+l][i] = m[i];
            }
            if (g >= 10 && g < 16 && l == 0) {          // pool CU3
                int pg = g - 10;
                int po = poolL[pg]*12 + poolR[pg]*3;
                float tt = pool[po], pp = pool[po+1], dd = pool[po+2];
                float ct = cosf(0.5f*tt), st = sinf(0.5f*tt);
                float2 m[16];
                #pragma unroll
                for (int i = 0; i < 16; i++) m[i] = make_float2(0.f, 0.f);
                m[0]  = make_float2(1.f, 0.f);
                m[5]  = make_float2(1.f, 0.f);
                m[10] = make_float2(ct, 0.f);
                m[11] = make_float2(-cosf(dd)*st, -sinf(dd)*st);
                m[14] = make_float2( cosf(pp)*st,  sinf(pp)*st);
                m[15] = make_float2( cosf(pp+dd)*ct, sinf(pp+dd)*ct);
                #pragma unroll
                for (int i = 0; i < 16; i++) elemBuf[50+pg][i] = m[i];
            }
            if (g == 15 && l >= 1) {                    // last-layer Paulis
                int k = l - 1;
                float th = last[k];
                float c = cosf(0.5f*th), s = sinf(0.5f*th);
                int wa = (k + 1) >> 2, wb = (k + 1) & 3;
                const float2 P[4][4] = {
                    { {1,0},{0,0},{0,0},{1,0} },
                    { {0,0},{1,0},{1,0},{0,0} },
                    { {0,0},{0,-1},{0,1},{0,0} },
                    { {1,0},{0,0},{0,0},{-1,0} }
                };
                float2 m[16];
                for (int gi = 0; gi < 4; gi++)
                    for (int h = 0; h < 4; h++) {
                        int ga = gi >> 1, gb = gi & 1, ha = h >> 1, hb = h & 1;
                        float2 wA = P[wa][ga*2+ha], wB = P[wb][gb*2+hb];
                        float2 W = cmul(wA, wB);
                        m[gi*4+h] = make_float2((gi == h ? c : 0.f) + s * W.y,
                                                -s * W.x);
                    }
                #pragma unroll
                for (int i = 0; i < 16; i++) elemBuf[56+k][i] = m[i];
            }
        }
        __syncthreads();

        // ---- merge gates 0..15 ----
        #pragma unroll
        for (int pass = 0; pass < 2; pass++) {
            int g = (t >> 4) + pass * 8;
            int r = (t >> 2) & 3, c = t & 3;
            int len = (g < 10) ? 5 : 1;
            int eb  = (g < 10) ? g*5 : 50 + (g - 10);
            int cur = 0;
            mgbuf[0][g][l] = elemBuf[eb][l];
            __syncwarp();
            for (int i = 1; i < len; i++) {
                float2 acc = make_float2(0.f, 0.f);
                #pragma unroll
                for (int k = 0; k < 4; k++)
                    acc = cfma(elemBuf[eb+i][r*4+k], mgbuf[cur][g][k*4+c], acc);
                mgbuf[cur^1][g][l] = acc;
                __syncwarp();
                cur ^= 1;
            }
            mged[g][l] = mgbuf[cur][g][l];
        }
        if (t < 16) {   // merge gate 16 (15-long chain)
            int r = t >> 2, c = t & 3, cur = 0;
            lastbuf[0][t] = elemBuf[56][t];
            __syncwarp(0x0000ffffu);
            for (int i = 1; i < 15; i++) {
                float2 acc = make_float2(0.f, 0.f);
                #pragma unroll
                for (int k = 0; k < 4; k++)
                    acc = cfma(elemBuf[56+i][r*4+k], lastbuf[cur][k*4+c], acc);
                lastbuf[cur^1][t] = acc;
                __syncwarp(0x0000ffffu);
                cur ^= 1;
            }
            mged[16][t] = lastbuf[cur][t];
        }
        __syncthreads();

        // ---- simulate: warps 0,1 each one column ----
        if (warp < 2) {
            const int appOrder[NMERGED] = {0,1,2,3,4,5,6, 10,11,12,13, 7,8,9, 14,15, 16};
            const int mba[NMERGED] = {7,5,3,1,6,4,2, 6,4,2,0, 7,3,5, 5,1, 7};
            const int mbb[NMERGED] = {6,4,2,0,5,3,1, 7,5,3,1, 5,1,3, 7,3, 3};
            const int col = bid * 2 + warp;
            for (int i = lane; i < 256; i += 32)
                amp[warp][i] = make_float2(i == col ? 1.f : 0.f, 0.f);
            __syncwarp();
            for (int gg = 0; gg < NMERGED; gg++) {
                int ba = mba[gg], bb = mbb[gg];
                int bl = min(ba, bb), bh = max(ba, bb);
                const int src = appOrder[gg];
                float2 m[16];
                #pragma unroll
                for (int i = 0; i < 16; i++) m[i] = mged[src][i];
                #pragma unroll
                for (int r = 0; r < 2; r++) {
                    int p = lane + 32 * r;
                    int q = ((p >> bl) << (bl + 1)) | (p & ((1 << bl) - 1));
                    int base = ((q >> bh) << (bh + 1)) | (q & ((1 << bh) - 1));
                    int i1 = base | (1 << bb);
                    int i2 = base | (1 << ba);
                    int i3 = i1 | i2;
                    float2 vv[4] = { amp[warp][base], amp[warp][i1],
                                     amp[warp][i2],   amp[warp][i3] };
                    float2 nv[4];
                    #pragma unroll
                    for (int a = 0; a < 4; a++) {
                        float2 acc = make_float2(0.f, 0.f);
                        #pragma unroll
                        for (int h = 0; h < 4; h++)
                            acc = cfma(m[a*4+h], vv[h], acc);
                        nv[a] = acc;
                    }
                    amp[warp][base] = nv[0]; amp[warp][i1] = nv[1];
                    amp[warp][i2]   = nv[2]; amp[warp][i3] = nv[3];
                }
                __syncwarp();
            }
            for (int k = lane; k < 256; k += 32)
                g_U[col * 256 + k] = amp[warp][k];
        }

        chain_bar(&g_barA);

        // ---- A tile: one 32x16 tile per block, full k ----
        {
            int i0 = (bid >> 4) * 32, j0 = (bid & 15) * 16;
            int ty = t >> 4, tx = t & 15;
            float accA[4] = {0.f, 0.f, 0.f, 0.f};
            for (int kc = 0; kc < 256; kc += 32) {
                for (int idx = t; idx < 1024; idx += NTHR) {
                    int row = idx >> 5, kk = idx & 31;
                    int k = kc + kk;
                    float sg = (k & 128) ? -1.f : 1.f;   // wire 0 <-> bit 7
                    float2 v = g_U[(i0 + row) * 256 + k];
                    sa[row][kk] = make_float2(v.x * sg, v.y * sg);
                }
                for (int idx = t; idx < 512; idx += NTHR) {
                    int row = idx >> 5, kk = idx & 31;
                    sb[row][kk] = g_U[(j0 + row) * 256 + kc + kk];
                }
                __syncthreads();
                #pragma unroll
                for (int kk = 0; kk < 32; kk++) {
                    float2 b = sb[tx][kk];
                    #pragma unroll
                    for (int q = 0; q < 4; q++) {
                        float2 a = sa[ty*4+q][kk];
                        accA[q] = fmaf(a.x, b.x, fmaf(a.y, b.y, accA[q]));
                    }
                }
                __syncthreads();
            }
            #pragma unroll
            for (int q = 0; q < 4; q++)
                g_A[(i0 + ty*4 + q) * 256 + j0 + tx] = accA[q];
        }

        chain_bar(&g_barB);

        // ---- stage1 ----
        for (int o = bid * NTHR + t; o < 81 * 256; o += N_CHAIN * NTHR) {
            int tt = o >> 8;
            int ilo = (o >> 4) & 15, jlo = o & 15;
            int d0 = tt / 27, r = tt % 27;
            int d1 = r / 9; r %= 9;
            int d2 = r / 3, d3 = r % 3;
            int dg[4] = { d0, d1, d2, d3 };
            float sum = 0.f;
            #pragma unroll
            for (int c = 0; c < 16; c++) {
                int ihi = 0, jhi = 0; float sg = 1.f;
                #pragma unroll
                for (int w = 0; w < 4; w++) {
                    int b = (c >> w) & 1;
                    int d = dg[w];
                    int jw = (d == 1) ? (1 - b) : b;
                    if (d == 2 && b) sg = -sg;
                    ihi |= b  << (3 - w);
                    jhi |= jw << (3 - w);
                }
                sum += sg * g_A[(ihi * 16 + ilo) * 256 + (jhi * 16 + jlo)];
            }
            g_T1[o] = sum;
        }

        chain_bar(&g_barC);

        // ---- stage2 ----
        for (int o = bid * NTHR + t; o < 6561; o += N_CHAIN * NTHR) {
            if (o < 243) g_C[o * 28 + 27] = 0.f;
            int thi = o / 81, tlo = o % 81;
            int d0 = tlo / 27, r = tlo % 27;
            int d1 = r / 9; r %= 9;
            int d2 = r / 3, d3 = r % 3;
            int dg[4] = { d0, d1, d2, d3 };
            float sum = 0.f;
            #pragma unroll
            for (int c = 0; c < 16; c++) {
                int ilo = 0, jlo = 0; float sg = 1.f;
                #pragma unroll
                for (int w = 0; w < 4; w++) {
                    int b = (c >> w) & 1;
                    int d = dg[w];
                    int jw = (d == 1) ? (1 - b) : b;
                    if (d == 2 && b) sg = -sg;
                    ilo |= b  << (3 - w);
                    jlo |= jw << (3 - w);
                }
                sum += sg * g_T1[thi * 256 + ilo * 16 + jlo];
            }
            g_C[(o / 27) * 28 + (o % 27)] = sum * (1.f / 256.f);
        }

        __threadfence();
        __syncthreads();
        if (t == 0) atomicAdd((int*)&g_done, 1);
    } else {
        // =================== GEMM + EVAL PATH (R5 shape: 2 rows/warp) ======
        int bg = bid - N_CHAIN;                       // 0..1023
        int row0 = bg * 8 + warp * 2;
        const ulonglong2* __restrict__ x0 =
            (const ulonglong2*)(x + (size_t)row0 * INPUT_DIM);
        const ulonglong2* __restrict__ x1 = x0 + (INPUT_DIM / 4);
        const ulonglong2* __restrict__ w4 = (const ulonglong2*)fcw;

        unsigned long long p0[8], p1[8];
        #pragma unroll
        for (int q = 0; q < 8; q++) { p0[q] = 0ull; p1[q] = 0ull; }

        #pragma unroll 4
        for (int kc = lane; kc < KVEC; kc += 32) {
            ulonglong2 xa = x0[kc];
            ulonglong2 xb = x1[kc];
            #pragma unroll
            for (int q = 0; q < 8; q++) {
                ulonglong2 wv = w4[q * KVEC + kc];
                p0[q] = ffma2(xa.x, wv.x, p0[q]);
                p0[q] = ffma2(xa.y, wv.y, p0[q]);
                p1[q] = ffma2(xb.x, wv.x, p1[q]);
                p1[q] = ffma2(xb.y, wv.y, p1[q]);
            }
        }
        float acc0[8], acc1[8];
        #pragma unroll
        for (int q = 0; q < 8; q++) {
            acc0[q] = __uint_as_float((unsigned)(p0[q] & 0xffffffffull))
                    + __uint_as_float((unsigned)(p0[q] >> 32));
            acc1[q] = __uint_as_float((unsigned)(p1[q] & 0xffffffffull))
                    + __uint_as_float((unsigned)(p1[q] >> 32));
        }
        #pragma unroll
        for (int q = 0; q < 8; q++) {
            #pragma unroll
            for (int off = 16; off > 0; off >>= 1) {
                acc0[q] += __shfl_xor_sync(0xffffffffu, acc0[q], off);
                acc1[q] += __shfl_xor_sync(0xffffffffu, acc1[q], off);
            }
        }

        // wait for the quantum chain (normally already done)
        if (t == 0) { while (g_done < N_CHAIN) { } }
        __syncthreads();
        __threadfence();

        // ---- eval: lanes 0-15 -> row0, lanes 16-31 -> row0+1 ----
        int half = lane >> 4;
        int part = lane & 15;
        float sn[8], cs[8];
        #pragma unroll
        for (int q = 0; q < 8; q++) {
            float f = tanhf((half ? acc1[q] : acc0[q]) + fcb[q]);
            __sincosf(f, &sn[q], &cs[q]);
        }

        float4 g4[7];
        {
            float* gp = (float*)g4;
            #pragma unroll
            for (int a = 0; a < 3; a++) {
                float ua = pick3(a, sn[5], cs[5]);
                #pragma unroll
                for (int b = 0; b < 3; b++) {
                    float uab = ua * pick3(b, sn[6], cs[6]);
                    #pragma unroll
                    for (int c = 0; c < 3; c++)
                        gp[a * 9 + b * 3 + c] = uab * pick3(c, sn[7], cs[7]);
                }
            }
            gp[27] = 0.f;
        }

        float qacc = 0.f;
        for (int o = part; o < 243; o += 16) {
            int d0 = o / 81, r = o % 81;
            int d1 = r / 27; r %= 27;
            int d2 = r / 9;  r %= 9;
            int d3 = r / 3,  d4 = r % 3;
            float p = pick3(d0, sn[0], cs[0]) * pick3(d1, sn[1], cs[1]);
            p *= pick3(d2, sn[2], cs[2]);
            p *= pick3(d3, sn[3], cs[3]);
            p *= pick3(d4, sn[4], cs[4]);
            const float4* crow = (const float4*)(g_C + o * 28);
            float dsum = 0.f;
            #pragma unroll
            for (int j = 0; j < 7; j++) {
                float4 cv = crow[j], gv = g4[j];
                dsum = fmaf(cv.x, gv.x, dsum);
                dsum = fmaf(cv.y, gv.y, dsum);
                dsum = fmaf(cv.z, gv.z, dsum);
                dsum = fmaf(cv.w, gv.w, dsum);
            }
            qacc = fmaf(p, dsum, qacc);
        }
        qacc += __shfl_xor_sync(0xffffffffu, qacc, 1);
        qacc += __shfl_xor_sync(0xffffffffu, qacc, 2);
        qacc += __shfl_xor_sync(0xffffffffu, qacc, 4);
        qacc += __shfl_xor_sync(0xffffffffu, qacc, 8);

        if (part < NCLS)
            logits[(row0 + half) * NCLS + part] = fmaf(qacc, outw[part], outb[part]);
    }

    // =================== epilogue: reset sync state for graph replay ========
    __syncthreads();
    if (t == 0) {
        int v = atomicAdd(&g_fin, 1);
        if (v == NGRID - 1) {
            g_barA = 0; g_barB = 0; g_barC = 0;
            *(int*)&g_done = 0;
            __threadfence();
            g_fin = 0;
        }
    }
}

// ---------------------------------------------------------------------------
extern "C" void kernel_launch(void* const* d_in, const int* in_sizes, int n_in,
                              void* d_out, int out_size)
{
    const float* x    = (const float*)d_in[0];
    const float* fcw  = (const float*)d_in[1];
    const float* fcb  = (const float*)d_in[2];
    const float* conv = (const float*)d_in[3];
    const float* pool = (const float*)d_in[4];
    const float* last = (const float*)d_in[5];
    const float* outw = (const float*)d_in[6];
    const float* outb = (const float*)d_in[7];
    float* out = (float*)d_out;

    mega<<<NGRID, NTHR>>>(x, fcw, fcb, conv, pool, last, outw, outb, out);
}

// round 8
// speedup vs baseline: 1.8762x; 1.8762x over previous
#include <cuda_runtime.h>
#include <math.h>

#define NQ 8
#define DIM 256
#define BATCH 8192
#define INPUT_DIM 3072
#define NCLS 10
#define NMERGED 17

#define N_CHAIN 128
#define N_GEMM 256
#define NGRID (N_CHAIN + N_GEMM)   // 384 blocks -> single wave at 3 blocks/SM
#define NTHR 256

// ---------------------------------------------------------------------------
// Device scratch + sync state
// ---------------------------------------------------------------------------
__device__ float2 g_U[DIM * DIM];                  // g_U[col*256 + k] = U[k][col]
__device__ float  g_A[DIM * DIM];
__device__ float  g_T1[81 * 256];
__device__ __align__(16) float g_C[243 * 28];      // padded rows (27 + 1)
__device__ int    g_barA, g_barB, g_barC;
__device__ volatile int g_done;
__device__ int    g_fin;

// ---------------------------------------------------------------------------
__device__ __forceinline__ float2 cmul(float2 a, float2 b) {
    return make_float2(a.x*b.x - a.y*b.y, a.x*b.y + a.y*b.x);
}
__device__ __forceinline__ float2 cfma(float2 a, float2 b, float2 c) {
    return make_float2(fmaf(a.x,b.x,fmaf(-a.y,b.y,c.x)),
                       fmaf(a.x,b.y,fmaf( a.y,b.x,c.y)));
}
__device__ __forceinline__ void u3fill(float t, float p, float d, float2 u[4]) {
    float ct = cosf(0.5f*t), st = sinf(0.5f*t);
    u[0] = make_float2(ct, 0.f);
    u[1] = make_float2(-cosf(d)*st, -sinf(d)*st);
    u[2] = make_float2( cosf(p)*st,  sinf(p)*st);
    u[3] = make_float2( cosf(p+d)*ct, sinf(p+d)*ct);
}
__device__ __forceinline__ unsigned long long ffma2(unsigned long long a,
                                                    unsigned long long b,
                                                    unsigned long long c) {
    unsigned long long d;
    asm("fma.rn.f32x2 %0, %1, %2, %3;" : "=l"(d) : "l"(a), "l"(b), "l"(c));
    return d;
}
__device__ __forceinline__ float f2lo(unsigned long long v) {
    return __uint_as_float((unsigned)(v & 0xffffffffull));
}
__device__ __forceinline__ float f2hi(unsigned long long v) {
    return __uint_as_float((unsigned)(v >> 32));
}
__device__ __forceinline__ float pick3(int d, float sn, float cs) {
    return (d == 0) ? 1.f : ((d == 1) ? sn : cs);
}
__device__ __forceinline__ void chain_bar(int* ctr) {
    __threadfence();
    __syncthreads();
    if (threadIdx.x == 0) {
        atomicAdd(ctr, 1);
        while (*(volatile int*)ctr < N_CHAIN) { }
    }
    __syncthreads();
}

// ---------------------------------------------------------------------------
// Shared memory union: chain phase 1 (gate build/merge/sim), chain phase 2
// (A tiles), gemm eval (C cache). Phases separated by chain_bar / syncthreads.
// ---------------------------------------------------------------------------
struct ChainP1 {
    float2 elemBuf[71][16];
    float2 mgbuf[2][16][16];
    float2 lastbuf[2][16];
    float2 mged[NMERGED][16];
    float2 amp[2][256];
};
struct ChainP2 {
    float2 sa[32][33];
    float2 sb[16][33];
};
union SmemU {
    ChainP1 p1;
    ChainP2 p2;
    float   sC[243 * 28];
};

// ---------------------------------------------------------------------------
__global__ void __launch_bounds__(NTHR, 3)
mega(const float* __restrict__ x,    const float* __restrict__ fcw,
     const float* __restrict__ fcb,  const float* __restrict__ conv,
     const float* __restrict__ pool, const float* __restrict__ last,
     const float* __restrict__ outw, const float* __restrict__ outb,
     float* __restrict__ logits)
{
    __shared__ SmemU sm;

    const int t = threadIdx.x;
    const int bid = blockIdx.x;
    const int warp = t >> 5, lane = t & 31;

    if (bid < N_CHAIN) {
        // =================== CHAIN PATH ===================
        const int convL[10] = {0,0,0,0,0,0,0,1,1,1};
        const int convI[10] = {0,2,4,6,1,3,5,0,2,1};
        const int poolL[6]  = {0,0,0,0,1,1};
        const int poolR[6]  = {0,1,2,3,0,1};
        const int g = t >> 4;           // 0..15 (256 threads)
        const int l = t & 15;

        // ---- build elementary 4x4 gates ----
        if (g < 10 && l < 5) {
            int L = convL[g], I = convI[g];
            const float* cw = conv + L * 120;
            float2 m[16];
            #pragma unroll
            for (int i = 0; i < 16; i++) m[i] = make_float2(0.f, 0.f);
            if (l == 0 || l == 4) {
                float2 ua[4], ub[4];
                if (l == 0) {
                    u3fill(cw[I*15+0],  cw[I*15+1],  cw[I*15+2],  ua);
                    u3fill(cw[(I+1)*15+3], cw[(I+1)*15+4], cw[(I+1)*15+5], ub);
                } else {
                    u3fill(cw[I*15+9],  cw[I*15+10], cw[I*15+11], ua);
                    u3fill(cw[(I+1)*15+12], cw[(I+1)*15+13], cw[(I+1)*15+14], ub);
                }
                for (int ga = 0; ga < 2; ga++)
                    for (int gb = 0; gb < 2; gb++)
                        for (int ha = 0; ha < 2; ha++)
                            for (int hb = 0; hb < 2; hb++)
                                m[(ga*2+gb)*4 + (ha*2+hb)] =
                                    cmul(ua[ga*2+ha], ub[gb*2+hb]);
            } else {
                float phi = cw[I*15 + 5 + l];
                float c = cosf(0.5f*phi), s = sinf(0.5f*phi);
                if (l == 1) {                       // ZZ
                    m[0]  = make_float2(c,-s); m[5]  = make_float2(c, s);
                    m[10] = make_float2(c, s); m[15] = make_float2(c,-s);
                } else if (l == 2) {                // YY
                    m[0]=m[5]=m[10]=m[15]=make_float2(c,0.f);
                    m[3]  = make_float2(0.f, s); m[6]  = make_float2(0.f,-s);
                    m[9]  = make_float2(0.f,-s); m[12] = make_float2(0.f, s);
                } else {                            // XX
                    m[0]=m[5]=m[10]=m[15]=make_float2(c,0.f);
                    m[3]=m[6]=m[9]=m[12]=make_float2(0.f,-s);
                }
            }
            #pragma unroll
            for (int i = 0; i < 16; i++) sm.p1.elemBuf[g*5+l][i] = m[i];
        }
        if (g >= 10 && g < 16 && l == 0) {          // pool CU3
            int pg = g - 10;
            int po = poolL[pg]*12 + poolR[pg]*3;
            float tt = pool[po], pp = pool[po+1], dd = pool[po+2];
            float ct = cosf(0.5f*tt), st = sinf(0.5f*tt);
            float2 m[16];
            #pragma unroll
            for (int i = 0; i < 16; i++) m[i] = make_float2(0.f, 0.f);
            m[0]  = make_float2(1.f, 0.f);
            m[5]  = make_float2(1.f, 0.f);
            m[10] = make_float2(ct, 0.f);
            m[11] = make_float2(-cosf(dd)*st, -sinf(dd)*st);
            m[14] = make_float2( cosf(pp)*st,  sinf(pp)*st);
            m[15] = make_float2( cosf(pp+dd)*ct, sinf(pp+dd)*ct);
            #pragma unroll
            for (int i = 0; i < 16; i++) sm.p1.elemBuf[50+pg][i] = m[i];
        }
        if (g == 15 && l >= 1) {                    // last-layer Paulis
            int k = l - 1;
            float th = last[k];
            float c = cosf(0.5f*th), s = sinf(0.5f*th);
            int wa = (k + 1) >> 2, wb = (k + 1) & 3;
            const float2 P[4][4] = {
                { {1,0},{0,0},{0,0},{1,0} },
                { {0,0},{1,0},{1,0},{0,0} },
                { {0,0},{0,-1},{0,1},{0,0} },
                { {1,0},{0,0},{0,0},{-1,0} }
            };
            float2 m[16];
            for (int gi = 0; gi < 4; gi++)
                for (int h = 0; h < 4; h++) {
                    int ga = gi >> 1, gb = gi & 1, ha = h >> 1, hb = h & 1;
                    float2 wA = P[wa][ga*2+ha], wB = P[wb][gb*2+hb];
                    float2 W = cmul(wA, wB);
                    m[gi*4+h] = make_float2((gi == h ? c : 0.f) + s * W.y,
                                            -s * W.x);
                }
            #pragma unroll
            for (int i = 0; i < 16; i++) sm.p1.elemBuf[56+k][i] = m[i];
        }
        __syncthreads();

        // ---- merge gates 0..15 (warp-uniform chain length) ----
        {
            int r = (t >> 2) & 3, cc = t & 3;
            int len = (g < 10) ? 5 : 1;
            int eb  = (g < 10) ? g*5 : 50 + (g - 10);
            int cur = 0;
            sm.p1.mgbuf[0][g][l] = sm.p1.elemBuf[eb][l];
            __syncwarp();
            for (int i = 1; i < len; i++) {
                float2 acc = make_float2(0.f, 0.f);
                #pragma unroll
                for (int k = 0; k < 4; k++)
                    acc = cfma(sm.p1.elemBuf[eb+i][r*4+k],
                               sm.p1.mgbuf[cur][g][k*4+cc], acc);
                sm.p1.mgbuf[cur^1][g][l] = acc;
                __syncwarp();
                cur ^= 1;
            }
            sm.p1.mged[g][l] = sm.p1.mgbuf[cur][g][l];
        }
        if (t < 16) {   // merge gate 16 (15-long chain)
            int r = t >> 2, cc = t & 3, cur = 0;
            sm.p1.lastbuf[0][t] = sm.p1.elemBuf[56][t];
            __syncwarp(0x0000ffffu);
            for (int i = 1; i < 15; i++) {
                float2 acc = make_float2(0.f, 0.f);
                #pragma unroll
                for (int k = 0; k < 4; k++)
                    acc = cfma(sm.p1.elemBuf[56+i][r*4+k],
                               sm.p1.lastbuf[cur][k*4+cc], acc);
                sm.p1.lastbuf[cur^1][t] = acc;
                __syncwarp(0x0000ffffu);
                cur ^= 1;
            }
            sm.p1.mged[16][t] = sm.p1.lastbuf[cur][t];
        }
        __syncthreads();

        // ---- simulate: warps 0,1 each one column ----
        if (warp < 2) {
            const int appOrder[NMERGED] = {0,1,2,3,4,5,6, 10,11,12,13, 7,8,9, 14,15, 16};
            const int mba[NMERGED] = {7,5,3,1,6,4,2, 6,4,2,0, 7,3,5, 5,1, 7};
            const int mbb[NMERGED] = {6,4,2,0,5,3,1, 7,5,3,1, 5,1,3, 7,3, 3};
            const int col = bid * 2 + warp;
            for (int i = lane; i < 256; i += 32)
                sm.p1.amp[warp][i] = make_float2(i == col ? 1.f : 0.f, 0.f);
            __syncwarp();
            for (int gg = 0; gg < NMERGED; gg++) {
                int ba = mba[gg], bb = mbb[gg];
                int bl = min(ba, bb), bh = max(ba, bb);
                const int src = appOrder[gg];
                float2 m[16];
                #pragma unroll
                for (int i = 0; i < 16; i++) m[i] = sm.p1.mged[src][i];
                #pragma unroll
                for (int r = 0; r < 2; r++) {
                    int p = lane + 32 * r;
                    int q = ((p >> bl) << (bl + 1)) | (p & ((1 << bl) - 1));
                    int base = ((q >> bh) << (bh + 1)) | (q & ((1 << bh) - 1));
                    int i1 = base | (1 << bb);
                    int i2 = base | (1 << ba);
                    int i3 = i1 | i2;
                    float2 vv[4] = { sm.p1.amp[warp][base], sm.p1.amp[warp][i1],
                                     sm.p1.amp[warp][i2],   sm.p1.amp[warp][i3] };
                    float2 nv[4];
                    #pragma unroll
                    for (int a = 0; a < 4; a++) {
                        float2 acc = make_float2(0.f, 0.f);
                        #pragma unroll
                        for (int h = 0; h < 4; h++)
                            acc = cfma(m[a*4+h], vv[h], acc);
                        nv[a] = acc;
                    }
                    sm.p1.amp[warp][base] = nv[0]; sm.p1.amp[warp][i1] = nv[1];
                    sm.p1.amp[warp][i2]   = nv[2]; sm.p1.amp[warp][i3] = nv[3];
                }
                __syncwarp();
            }
            for (int k = lane; k < 256; k += 32)
                g_U[col * 256 + k] = sm.p1.amp[warp][k];
        }

        chain_bar(&g_barA);

        // ---- A tile: one 32x16 tile per block ----
        {
            int i0 = (bid >> 4) * 32, j0 = (bid & 15) * 16;
            int ty = t >> 4, tx = t & 15;     // 16x16
            float accA[2] = {0.f, 0.f};
            for (int kc = 0; kc < 256; kc += 32) {
                for (int idx = t; idx < 1024; idx += NTHR) {
                    int row = idx >> 5, kk = idx & 31;
                    int k = kc + kk;
                    float sg = (k & 128) ? -1.f : 1.f;   // wire 0 <-> bit 7
                    float2 v = g_U[(i0 + row) * 256 + k];
                    sm.p2.sa[row][kk] = make_float2(v.x * sg, v.y * sg);
                }
                for (int idx = t; idx < 512; idx += NTHR) {
                    int row = idx >> 5, kk = idx & 31;
                    sm.p2.sb[row][kk] = g_U[(j0 + row) * 256 + kc + kk];
                }
                __syncthreads();
                #pragma unroll
                for (int kk = 0; kk < 32; kk++) {
                    float2 b = sm.p2.sb[tx][kk];
                    #pragma unroll
                    for (int q = 0; q < 2; q++) {
                        float2 a = sm.p2.sa[ty*2+q][kk];
                        accA[q] = fmaf(a.x, b.x, fmaf(a.y, b.y, accA[q]));
                    }
                }
                __syncthreads();
            }
            #pragma unroll
            for (int q = 0; q < 2; q++)
                g_A[(i0 + ty*2 + q) * 256 + j0 + tx] = accA[q];
        }

        chain_bar(&g_barB);

        // ---- stage1 (single pass: 128*256 = 32768 >= 20736) ----
        {
            int o = bid * NTHR + t;
            if (o < 81 * 256) {
                int tt = o >> 8;
                int ilo = (o >> 4) & 15, jlo = o & 15;
                int d0 = tt / 27, r = tt % 27;
                int d1 = r / 9; r %= 9;
                int d2 = r / 3, d3 = r % 3;
                int dg[4] = { d0, d1, d2, d3 };
                float sum = 0.f;
                #pragma unroll
                for (int c = 0; c < 16; c++) {
                    int ihi = 0, jhi = 0; float sg = 1.f;
                    #pragma unroll
                    for (int w = 0; w < 4; w++) {
                        int b = (c >> w) & 1;
                        int d = dg[w];
                        int jw = (d == 1) ? (1 - b) : b;
                        if (d == 2 && b) sg = -sg;
                        ihi |= b  << (3 - w);
                        jhi |= jw << (3 - w);
                    }
                    sum += sg * g_A[(ihi * 16 + ilo) * 256 + (jhi * 16 + jlo)];
                }
                g_T1[o] = sum;
            }
        }

        chain_bar(&g_barC);

        // ---- stage2 (single pass: 6561 < 32768) ----
        {
            int o = bid * NTHR + t;
            if (o < 6561) {
                if (o < 243) g_C[o * 28 + 27] = 0.f;
                int thi = o / 81, tlo = o % 81;
                int d0 = tlo / 27, r = tlo % 27;
                int d1 = r / 9; r %= 9;
                int d2 = r / 3, d3 = r % 3;
                int dg[4] = { d0, d1, d2, d3 };
                float sum = 0.f;
                #pragma unroll
                for (int c = 0; c < 16; c++) {
                    int ilo = 0, jlo = 0; float sg = 1.f;
                    #pragma unroll
                    for (int w = 0; w < 4; w++) {
                        int b = (c >> w) & 1;
                        int d = dg[w];
                        int jw = (d == 1) ? (1 - b) : b;
                        if (d == 2 && b) sg = -sg;
                        ilo |= b  << (3 - w);
                        jlo |= jw << (3 - w);
                    }
                    sum += sg * g_T1[thi * 256 + ilo * 16 + jlo];
                }
                g_C[(o / 27) * 28 + (o % 27)] = sum * (1.f / 256.f);
            }
        }

        __threadfence();
        __syncthreads();
        if (t == 0) atomicAdd((int*)&g_done, 1);
    } else {
        // =================== GEMM + EVAL PATH ===================
        // warp = 4 rows x 8 k-lanes. Per 32-float chunk: 1 coalesced x-LDG.128
        // (4 lines) + 8 single-line (broadcast) w-LDG.128.
        int bg = bid - N_CHAIN;                       // 0..255
        const int klane = lane & 7;
        const int rsel = lane >> 3;                   // 0..3
        const int row = bg * 32 + warp * 4 + rsel;
        const ulonglong2* __restrict__ xr =
            (const ulonglong2*)(x + (size_t)row * INPUT_DIM);
        const ulonglong2* __restrict__ wp = (const ulonglong2*)fcw;

        unsigned long long acc[8];
        #pragma unroll
        for (int q = 0; q < 8; q++) acc[q] = 0ull;

        for (int c = 0; c < 96; c += 4) {
            ulonglong2 xs[4];
            #pragma unroll
            for (int u = 0; u < 4; u++)
                xs[u] = xr[(c + u) * 8 + klane];
            #pragma unroll
            for (int u = 0; u < 4; u++) {
                ulonglong2 wv[8];
                #pragma unroll
                for (int q = 0; q < 8; q++)
                    wv[q] = wp[q * 768 + (c + u) * 8 + klane];
                #pragma unroll
                for (int q = 0; q < 8; q++) {
                    acc[q] = ffma2(xs[u].x, wv[q].x, acc[q]);
                    acc[q] = ffma2(xs[u].y, wv[q].y, acc[q]);
                }
            }
        }

        // fold f32x2 and reduce across the 8 k-lanes of each row
        float av[8];
        #pragma unroll
        for (int q = 0; q < 8; q++) {
            float v = f2lo(acc[q]) + f2hi(acc[q]);
            v += __shfl_xor_sync(0xffffffffu, v, 1);
            v += __shfl_xor_sync(0xffffffffu, v, 2);
            v += __shfl_xor_sync(0xffffffffu, v, 4);
            av[q] = v;                                // row-complete on all 8 klanes
        }

        float sn[8], cs[8];
        #pragma unroll
        for (int q = 0; q < 8; q++) {
            float f = tanhf(av[q] + fcb[q]);
            __sincosf(f, &sn[q], &cs[q]);
        }

        // wait for the quantum chain, then cache C in shared
        if (t == 0) { while (g_done < N_CHAIN) { } }
        __syncthreads();
        for (int i = t; i < (243 * 28) / 4; i += NTHR)
            ((float4*)sm.sC)[i] = ((const float4*)g_C)[i];
        __syncthreads();

        // per-row eval: 8 k-lanes split the 243 outer rows; C rows broadcast
        float4 g4[7];
        {
            float* gp = (float*)g4;
            #pragma unroll
            for (int a = 0; a < 3; a++) {
                float ua = pick3(a, sn[5], cs[5]);
                #pragma unroll
                for (int b = 0; b < 3; b++) {
                    float uab = ua * pick3(b, sn[6], cs[6]);
                    #pragma unroll
                    for (int c = 0; c < 3; c++)
                        gp[a * 9 + b * 3 + c] = uab * pick3(c, sn[7], cs[7]);
                }
            }
            gp[27] = 0.f;
        }

        float qacc = 0.f;
        for (int o = klane; o < 243; o += 8) {
            int d0 = o / 81, r = o % 81;
            int d1 = r / 27; r %= 27;
            int d2 = r / 9;  r %= 9;
            int d3 = r / 3,  d4 = r % 3;
            float p = pick3(d0, sn[0], cs[0]) * pick3(d1, sn[1], cs[1]);
            p *= pick3(d2, sn[2], cs[2]);
            p *= pick3(d3, sn[3], cs[3]);
            p *= pick3(d4, sn[4], cs[4]);
            const float4* crow = (const float4*)(sm.sC + o * 28);
            float dsum = 0.f;
            #pragma unroll
            for (int j = 0; j < 7; j++) {
                float4 cv = crow[j], gv = g4[j];
                dsum = fmaf(cv.x, gv.x, dsum);
                dsum = fmaf(cv.y, gv.y, dsum);
                dsum = fmaf(cv.z, gv.z, dsum);
                dsum = fmaf(cv.w, gv.w, dsum);
            }
            qacc = fmaf(p, dsum, qacc);
        }
        qacc += __shfl_xor_sync(0xffffffffu, qacc, 1);
        qacc += __shfl_xor_sync(0xffffffffu, qacc, 2);
        qacc += __shfl_xor_sync(0xffffffffu, qacc, 4);

        // write logits: klane covers cls {klane, klane+8}
        logits[row * NCLS + klane] = fmaf(qacc, outw[klane], outb[klane]);
        if (klane < 2)
            logits[row * NCLS + klane + 8] =
                fmaf(qacc, outw[klane + 8], outb[klane + 8]);
    }

    // =================== epilogue: reset sync state for graph replay ========
    __syncthreads();
    if (t == 0) {
        int v = atomicAdd(&g_fin, 1);
        if (v == NGRID - 1) {
            g_barA = 0; g_barB = 0; g_barC = 0;
            *(int*)&g_done = 0;
            __threadfence();
            g_fin = 0;
        }
    }
}

// ---------------------------------------------------------------------------
extern "C" void kernel_launch(void* const* d_in, const int* in_sizes, int n_in,
                              void* d_out, int out_size)
{
    const float* x    = (const float*)d_in[0];
    const float* fcw  = (const float*)d_in[1];
    const float* fcb  = (const float*)d_in[2];
    const float* conv = (const float*)d_in[3];
    const float* pool = (const float*)d_in[4];
    const float* last = (const float*)d_in[5];
    const float* outw = (const float*)d_in[6];
    const float* outb = (const float*)d_in[7];
    float* out = (float*)d_out;

    mega<<<NGRID, NTHR>>>(x, fcw, fcb, conv, pool, last, outw, outb, out);
}